// round 3
// baseline (speedup 1.0000x reference)
#include <cuda_runtime.h>
#include <cstddef>

#define NNODES 50000
#define NPER   25000
#define NEDGE  600000
#define RREL   8
#define NB     4
#define INDIM  256
#define HID    128
#define OUTD2  64
#define NSEG   (NNODES * RREL)          // 400000
#define KAGG   (RREL * HID)             // 1024
#define KCONV  (KAGG + HID)             // 1152

// ---------------- scratch (device globals: no allocation allowed) ----------
__device__ float g_agg[(size_t)NSEG * HID];          // 204.8 MB
__device__ float g_norm[NSEG];                        // counts -> 1/max(cnt,1)
__device__ float g_wstack[KCONV * HID];               // stacked [W_r ; root]
__device__ float g_x2[(size_t)NNODES * HID];          // h0 + relu(conv1)
__device__ int   g_is64;                              // edge index dtype flag

// ---------------- edge dtype detection -------------------------------------
__global__ void detect_kernel(const int* p) {
    if (blockIdx.x == 0 && threadIdx.x == 0) {
        int any = 0;
        #pragma unroll 8
        for (int i = 1; i < 2048; i += 2) any |= p[i];
        g_is64 = (any == 0) ? 1 : 0;   // int64 values < 2^31 => all high words 0
    }
}

__device__ __forceinline__ int ld_idx(const void* p, long i) {
    return g_is64 ? (int)((const long long*)p)[i] : ((const int*)p)[i];
}

// ---------------- zero / degree / norm --------------------------------------
__global__ void zero_agg_kernel() {
    size_t i = (size_t)blockIdx.x * blockDim.x + threadIdx.x;
    size_t st = (size_t)gridDim.x * blockDim.x;
    float4 z = make_float4(0.f, 0.f, 0.f, 0.f);
    float4* p = (float4*)g_agg;
    size_t n4 = ((size_t)NSEG * HID) / 4;
    for (; i < n4; i += st) p[i] = z;
}

__global__ void zero_norm_kernel() {
    int i = blockIdx.x * blockDim.x + threadIdx.x;
    if (i < NSEG) g_norm[i] = 0.f;
}

__global__ void count_kernel(const void* ei, const void* et) {
    int e = blockIdx.x * blockDim.x + threadIdx.x;
    if (e >= NEDGE) return;
    int dst = ld_idx(ei, (long)NEDGE + e);
    int t   = ld_idx(et, e);
    atomicAdd(&g_norm[dst * RREL + t], 1.0f);
}

__global__ void norm_inv_kernel() {
    int i = blockIdx.x * blockDim.x + threadIdx.x;
    if (i < NSEG) g_norm[i] = 1.0f / fmaxf(g_norm[i], 1.0f);
}

// ---------------- weight stacking: [comp@bases (R*HID rows) ; root] --------
__global__ void wstack_kernel(const float* __restrict__ bases,
                              const float* __restrict__ comp,
                              const float* __restrict__ root, int outd) {
    int idx = blockIdx.x * blockDim.x + threadIdx.x;
    int total = KCONV * outd;
    if (idx >= total) return;
    int k = idx / outd, o = idx % outd;
    if (k < KAGG) {
        int r = k / HID, i = k % HID;
        float s = 0.f;
        #pragma unroll
        for (int b = 0; b < NB; b++)
            s += comp[r * NB + b] * bases[((size_t)b * HID + i) * outd + o];
        g_wstack[idx] = s;
    } else {
        g_wstack[idx] = root[(size_t)(k - KAGG) * outd + o];
    }
}

// ---------------- edge scatter: agg[dst*R+t] += x[src] (one warp / edge) ---
template<int XSRC>
__global__ void scatter_kernel(const void* ei, const void* et,
                               const float* __restrict__ xp) {
    int e = blockIdx.x * 8 + (threadIdx.x >> 5);
    if (e >= NEDGE) return;
    int lane = threadIdx.x & 31;
    const float* x = XSRC ? (const float*)g_x2 : xp;
    int src = ld_idx(ei, e);
    int dst = ld_idx(ei, (long)NEDGE + e);
    int t   = ld_idx(et, e);
    float4 v = ((const float4*)(x + (size_t)src * HID))[lane];
    float* a = g_agg + ((size_t)dst * RREL + t) * HID + lane * 4;
    atomicAdd(a + 0, v.x); atomicAdd(a + 1, v.y);
    atomicAdd(a + 2, v.z); atomicAdd(a + 3, v.w);
}

// ---------------- input projection GEMM: relu(x@W+b) -> two destinations ---
__global__ void __launch_bounds__(256)
proj_gemm(const float* __restrict__ xin, const float* __restrict__ W,
          const float* __restrict__ bias,
          float* __restrict__ o1, float* __restrict__ o2) {
    constexpr int BM = 64, BK = 16, ON = HID, TN = ON / 16;
    __shared__ __align__(16) float As[BK][BM];
    __shared__ __align__(16) float Bs[BK][ON];
    int bm = blockIdx.x * BM;
    int tid = threadIdx.x, tx = tid & 15, ty = tid >> 4;
    int arow = tid >> 2, asub = (tid & 3) * 4;
    int n = bm + arow;
    bool rowok = n < NPER;
    float acc[4][TN] = {};
    for (int k0 = 0; k0 < INDIM; k0 += BK) {
        float4 v = make_float4(0.f, 0.f, 0.f, 0.f);
        if (rowok) v = *(const float4*)(xin + (size_t)n * INDIM + k0 + asub);
        As[asub + 0][arow] = v.x; As[asub + 1][arow] = v.y;
        As[asub + 2][arow] = v.z; As[asub + 3][arow] = v.w;
        const float* bsrc = W + (size_t)k0 * ON;
        #pragma unroll
        for (int i = tid * 4; i < BK * ON; i += 1024)
            *(float4*)((float*)Bs + i) = *(const float4*)(bsrc + i);
        __syncthreads();
        #pragma unroll
        for (int k = 0; k < BK; k++) {
            float4 a4 = *(float4*)&As[k][ty * 4];
            float av[4] = {a4.x, a4.y, a4.z, a4.w};
            float bv[TN];
            #pragma unroll
            for (int j = 0; j < TN; j += 4) {
                float4 b4 = *(float4*)&Bs[k][tx * TN + j];
                bv[j] = b4.x; bv[j + 1] = b4.y; bv[j + 2] = b4.z; bv[j + 3] = b4.w;
            }
            #pragma unroll
            for (int i = 0; i < 4; i++)
                #pragma unroll
                for (int j = 0; j < TN; j++)
                    acc[i][j] = fmaf(av[i], bv[j], acc[i][j]);
        }
        __syncthreads();
    }
    #pragma unroll
    for (int i = 0; i < 4; i++) {
        int m = bm + ty * 4 + i;
        if (m >= NPER) break;
        #pragma unroll
        for (int j = 0; j < TN; j++) {
            int o = tx * TN + j;
            float v = fmaxf(acc[i][j] + bias[o], 0.f);
            o1[(size_t)m * HID + o] = v;
            o2[(size_t)m * HID + o] = v;
        }
    }
}

// ---------------- conv GEMM: [50k,1152] @ wstack[1152,OUTD] + bias ---------
// A[n,k] = k<1024 ? agg[n,k]*norm[n, k/128] : x[n, k-1024]
// MODE 0: relu  | 1: relu + resid | 2: plain
template<int ON, int MODE, int XSRC, int ODST>
__global__ void __launch_bounds__(256)
conv_gemm(const float* __restrict__ x, const float* __restrict__ bias,
          const float* __restrict__ resid, float* __restrict__ outp) {
    constexpr int BM = 64, BK = 16, TN = ON / 16;
    __shared__ __align__(16) float As[BK][BM];
    __shared__ __align__(16) float Bs[BK][ON];
    int bm = blockIdx.x * BM;
    int tid = threadIdx.x, tx = tid & 15, ty = tid >> 4;
    int arow = tid >> 2, asub = (tid & 3) * 4;
    int n = bm + arow;
    bool rowok = n < NNODES;
    const float* xbase = XSRC ? (const float*)g_x2 : x;
    const float* aggrow = g_agg + (size_t)n * KAGG;
    const float* xrow = xbase + (size_t)n * HID;
    float acc[4][TN] = {};
    for (int k0 = 0; k0 < KCONV; k0 += BK) {
        int g = k0 + asub;
        float4 v = make_float4(0.f, 0.f, 0.f, 0.f);
        if (rowok) {
            if (g < KAGG) {
                v = *(const float4*)(aggrow + g);
                float s = g_norm[(size_t)n * RREL + (g >> 7)];
                v.x *= s; v.y *= s; v.z *= s; v.w *= s;
            } else {
                v = *(const float4*)(xrow + (g - KAGG));
            }
        }
        As[asub + 0][arow] = v.x; As[asub + 1][arow] = v.y;
        As[asub + 2][arow] = v.z; As[asub + 3][arow] = v.w;
        const float* bsrc = g_wstack + (size_t)k0 * ON;
        #pragma unroll
        for (int i = tid * 4; i < BK * ON; i += 1024)
            *(float4*)((float*)Bs + i) = *(const float4*)(bsrc + i);
        __syncthreads();
        #pragma unroll
        for (int k = 0; k < BK; k++) {
            float4 a4 = *(float4*)&As[k][ty * 4];
            float av[4] = {a4.x, a4.y, a4.z, a4.w};
            float bv[TN];
            #pragma unroll
            for (int j = 0; j < TN; j += 4) {
                float4 b4 = *(float4*)&Bs[k][tx * TN + j];
                bv[j] = b4.x; bv[j + 1] = b4.y; bv[j + 2] = b4.z; bv[j + 3] = b4.w;
            }
            #pragma unroll
            for (int i = 0; i < 4; i++)
                #pragma unroll
                for (int j = 0; j < TN; j++)
                    acc[i][j] = fmaf(av[i], bv[j], acc[i][j]);
        }
        __syncthreads();
    }
    float* obase = ODST ? (float*)g_x2 : outp;
    #pragma unroll
    for (int i = 0; i < 4; i++) {
        int m = bm + ty * 4 + i;
        if (m >= NNODES) break;
        #pragma unroll
        for (int j = 0; j < TN; j++) {
            int o = tx * TN + j;
            float v = acc[i][j] + bias[o];
            if (MODE == 0) v = fmaxf(v, 0.f);
            else if (MODE == 1) v = fmaxf(v, 0.f) + resid[(size_t)m * ON + o];
            obase[(size_t)m * ON + o] = v;
        }
    }
}

// ---------------- launch ----------------------------------------------------
extern "C" void kernel_launch(void* const* d_in, const int* in_sizes, int n_in,
                              void* d_out, int out_size) {
    const float* x_paper  = (const float*)d_in[0];
    const float* x_author = (const float*)d_in[1];
    const float* W_paper  = (const float*)d_in[2];
    const float* b_paper  = (const float*)d_in[3];
    const float* W_author = (const float*)d_in[4];
    const float* b_author = (const float*)d_in[5];
    const float* bases0 = (const float*)d_in[6];
    const float* comp0  = (const float*)d_in[7];
    const float* root0  = (const float*)d_in[8];
    const float* bias0  = (const float*)d_in[9];
    const float* bases1 = (const float*)d_in[10];
    const float* comp1  = (const float*)d_in[11];
    const float* root1  = (const float*)d_in[12];
    const float* bias1  = (const float*)d_in[13];
    const float* bases2 = (const float*)d_in[14];
    const float* comp2  = (const float*)d_in[15];
    const float* root2  = (const float*)d_in[16];
    const float* bias2  = (const float*)d_in[17];
    const void*  edge_index = d_in[18];
    const void*  edge_type  = d_in[19];

    // output pytree flat order: out [N,64], x_init, x_init, h0 (each [N,128])
    float* out0 = (float*)d_out;
    float* lat0 = out0 + (size_t)NNODES * OUTD2;
    float* lat1 = lat0 + (size_t)NNODES * HID;
    float* lat2 = lat1 + (size_t)NNODES * HID;

    const int T = 256;
    const int gseg   = (NSEG + T - 1) / T;
    const int gedge  = (NEDGE + T - 1) / T;
    const int gscat  = (NEDGE + 7) / 8;
    const int gproj  = (NPER + 63) / 64;
    const int gconv  = (NNODES + 63) / 64;

    // edge dtype + degree norm (once; reused by all convs)
    detect_kernel<<<1, 32>>>((const int*)edge_index);
    zero_norm_kernel<<<gseg, T>>>();
    count_kernel<<<gedge, T>>>(edge_index, edge_type);
    norm_inv_kernel<<<gseg, T>>>();

    // input projections -> x_init written to both latent slots
    proj_gemm<<<gproj, T>>>(x_paper, W_paper, b_paper, lat0, lat1);
    proj_gemm<<<gproj, T>>>(x_author, W_author, b_author,
                            lat0 + (size_t)NPER * HID, lat1 + (size_t)NPER * HID);

    // conv0: x = x_init (lat0), out h0 -> lat2
    wstack_kernel<<<(KCONV * HID + T - 1) / T, T>>>(bases0, comp0, root0, HID);
    zero_agg_kernel<<<4096, T>>>();
    scatter_kernel<0><<<gscat, T>>>(edge_index, edge_type, lat0);
    conv_gemm<HID, 0, 0, 0><<<gconv, T>>>(lat0, bias0, nullptr, lat2);

    // conv1: x = h0 (lat2), out x2 = h0 + relu(.) -> g_x2
    wstack_kernel<<<(KCONV * HID + T - 1) / T, T>>>(bases1, comp1, root1, HID);
    zero_agg_kernel<<<4096, T>>>();
    scatter_kernel<0><<<gscat, T>>>(edge_index, edge_type, lat2);
    conv_gemm<HID, 1, 0, 1><<<gconv, T>>>(lat2, bias1, lat2, nullptr);

    // conv2: x = g_x2, out -> out0 (no relu)
    wstack_kernel<<<(KCONV * OUTD2 + T - 1) / T, T>>>(bases2, comp2, root2, OUTD2);
    zero_agg_kernel<<<4096, T>>>();
    scatter_kernel<1><<<gscat, T>>>(edge_index, edge_type, nullptr);
    conv_gemm<OUTD2, 2, 1, 0><<<gconv, T>>>(nullptr, bias2, nullptr, out0);
}

// round 4
// speedup vs baseline: 2.0499x; 2.0499x over previous
#include <cuda_runtime.h>
#include <cstddef>

#define NNODES 50000
#define NPER   25000
#define NEDGE  600000
#define RREL   8
#define NB     4
#define INDIM  256
#define HID    128
#define OUTD2  64
#define NSEG   (NNODES * RREL)   // 400000
#define KFUSE  (NB * HID + HID)  // 640
#define KPAD   644               // padded A-tile row stride (floats)

// ---------------- scratch (device globals: no allocation allowed) ----------
__device__ int   g_cnt[NSEG];            // per-(dst,rel) edge counts
__device__ float g_norm[NSEG];           // 1/max(cnt,1)
__device__ int   g_fill[NNODES];         // CSR fill cursors
__device__ int   g_rowptr[NNODES + 1];   // CSR row pointers (by dst)
__device__ int   g_ecsr[NEDGE];          // packed src*8+etype, sorted by dst
__device__ float g_x2[(size_t)NNODES * HID];  // x2 = h0 + relu(conv1)
__device__ int   g_is64;                 // edge index dtype flag

// ---------------- edge dtype detection -------------------------------------
__global__ void detect_kernel(const int* p) {
    if (blockIdx.x == 0 && threadIdx.x == 0) {
        int any = 0;
        #pragma unroll 8
        for (int i = 1; i < 2048; i += 2) any |= p[i];
        g_is64 = (any == 0) ? 1 : 0;   // values < 2^31 => int64 high words all 0
    }
}

__device__ __forceinline__ int ld_idx(const void* p, long i) {
    return g_is64 ? (int)((const long long*)p)[i] : ((const int*)p)[i];
}

// ---------------- pre-stages: counts, norm, CSR ------------------------------
__global__ void zero_pre_kernel() {
    int i = blockIdx.x * blockDim.x + threadIdx.x;
    if (i < NSEG) g_cnt[i] = 0;
    else if (i < NSEG + NNODES) g_fill[i - NSEG] = 0;
}

__global__ void count_kernel(const void* ei, const void* et) {
    int e = blockIdx.x * blockDim.x + threadIdx.x;
    if (e >= NEDGE) return;
    int dst = ld_idx(ei, (long)NEDGE + e);
    int t   = ld_idx(et, e);
    atomicAdd(&g_cnt[dst * RREL + t], 1);
}

__global__ void norm_inv_kernel() {
    int i = blockIdx.x * blockDim.x + threadIdx.x;
    if (i < NSEG) g_norm[i] = 1.0f / fmaxf((float)g_cnt[i], 1.0f);
}

// single-block exclusive scan of per-dst degrees (sum of 8 relation counts)
__global__ void scan_kernel() {
    __shared__ int wsum[32];
    __shared__ int sbase;
    int tid = threadIdx.x, lane = tid & 31, wid = tid >> 5;
    if (tid == 0) sbase = 0;
    __syncthreads();
    for (int base = 0; base < NNODES; base += 1024) {
        int n = base + tid;
        int d = 0;
        if (n < NNODES) {
            #pragma unroll
            for (int r = 0; r < RREL; r++) d += g_cnt[n * RREL + r];
        }
        int s = d;
        #pragma unroll
        for (int off = 1; off < 32; off <<= 1) {
            int t = __shfl_up_sync(0xffffffffu, s, off);
            if (lane >= off) s += t;
        }
        if (lane == 31) wsum[wid] = s;
        __syncthreads();
        if (wid == 0) {
            int w = wsum[lane];
            #pragma unroll
            for (int off = 1; off < 32; off <<= 1) {
                int t = __shfl_up_sync(0xffffffffu, w, off);
                if (lane >= off) w += t;
            }
            wsum[lane] = w;
        }
        __syncthreads();
        int pre = sbase + (wid > 0 ? wsum[wid - 1] : 0) + s - d;  // exclusive
        if (n < NNODES) g_rowptr[n] = pre;
        __syncthreads();
        if (tid == 1023) sbase += wsum[31];
        __syncthreads();
    }
    if (threadIdx.x == 0) g_rowptr[NNODES] = sbase;
}

__global__ void csr_fill_kernel(const void* ei, const void* et) {
    int e = blockIdx.x * blockDim.x + threadIdx.x;
    if (e >= NEDGE) return;
    int src = ld_idx(ei, e);
    int dst = ld_idx(ei, (long)NEDGE + e);
    int t   = ld_idx(et, e);
    int pos = g_rowptr[dst] + atomicAdd(&g_fill[dst], 1);
    g_ecsr[pos] = src * RREL + t;
}

// ---------------- input projection GEMM: relu(x@W+b) -> two destinations ---
__global__ void __launch_bounds__(256)
proj_gemm(const float* __restrict__ xin, const float* __restrict__ W,
          const float* __restrict__ bias,
          float* __restrict__ o1, float* __restrict__ o2) {
    constexpr int BM = 64, BK = 16, ON = HID, TN = ON / 16;
    __shared__ __align__(16) float As[BK][BM];
    __shared__ __align__(16) float Bs[BK][ON];
    int bm = blockIdx.x * BM;
    int tid = threadIdx.x, tx = tid & 15, ty = tid >> 4;
    int arow = tid >> 2, asub = (tid & 3) * 4;
    int n = bm + arow;
    bool rowok = n < NPER;
    float acc[4][TN] = {};
    for (int k0 = 0; k0 < INDIM; k0 += BK) {
        float4 v = make_float4(0.f, 0.f, 0.f, 0.f);
        if (rowok) v = *(const float4*)(xin + (size_t)n * INDIM + k0 + asub);
        As[asub + 0][arow] = v.x; As[asub + 1][arow] = v.y;
        As[asub + 2][arow] = v.z; As[asub + 3][arow] = v.w;
        const float* bsrc = W + (size_t)k0 * ON;
        #pragma unroll
        for (int i = tid * 4; i < BK * ON; i += 1024)
            *(float4*)((float*)Bs + i) = *(const float4*)(bsrc + i);
        __syncthreads();
        #pragma unroll
        for (int k = 0; k < BK; k++) {
            float4 a4 = *(float4*)&As[k][ty * 4];
            float av[4] = {a4.x, a4.y, a4.z, a4.w};
            float bv[TN];
            #pragma unroll
            for (int j = 0; j < TN; j += 4) {
                float4 b4 = *(float4*)&Bs[k][tx * TN + j];
                bv[j] = b4.x; bv[j + 1] = b4.y; bv[j + 2] = b4.z; bv[j + 3] = b4.w;
            }
            #pragma unroll
            for (int i = 0; i < 4; i++)
                #pragma unroll
                for (int j = 0; j < TN; j++)
                    acc[i][j] = fmaf(av[i], bv[j], acc[i][j]);
        }
        __syncthreads();
    }
    #pragma unroll
    for (int i = 0; i < 4; i++) {
        int m = bm + ty * 4 + i;
        if (m >= NPER) break;
        #pragma unroll
        for (int j = 0; j < TN; j++) {
            int o = tx * TN + j;
            float v = fmaxf(acc[i][j] + bias[o], 0.f);
            o1[(size_t)m * HID + o] = v;
            o2[(size_t)m * HID + o] = v;
        }
    }
}

// ---------------- fully fused conv ------------------------------------------
// Per block: 32 dst nodes. Phase 1: per-warp register aggregation of the 4
// basis planes aggB_b[dst] = sum_edges (norm*comp[et,b]) * x[src], plus the
// x[dst] row, staged into a 32x640 smem A-tile. Phase 2: A @ [bases;root]
// with bias + relu/residual epilogue. No atomics, no global intermediates.
// MODE 0: relu | 1: relu + resid | 2: plain.
template<int OUTD, int MODE, int XIN2, int YOUT2>
__global__ void __launch_bounds__(256, 2)
fused_conv(const float* __restrict__ xg,
           const float* __restrict__ comp,
           const float* __restrict__ bases,
           const float* __restrict__ root,
           const float* __restrict__ bias,
           const float* __restrict__ resid,
           float* __restrict__ yg) {
    extern __shared__ float sm[];
    float* As = sm;                        // [32][KPAD]
    float* Bs = sm + 32 * KPAD;            // [16][OUTD]
    float* comp_s = Bs + 16 * OUTD;        // [32] = comp[8][4]
    const float* x = XIN2 ? (const float*)g_x2 : xg;
    float* y = YOUT2 ? (float*)g_x2 : yg;

    int tid = threadIdx.x;
    int n0 = blockIdx.x * 32;
    if (tid < 32) comp_s[tid] = comp[tid];
    __syncthreads();

    // ---- phase 1: aggregation in registers ----
    {
        int lane = tid & 31, w = tid >> 5;
        #pragma unroll
        for (int i = 0; i < 4; i++) {
            int m = w * 4 + i;
            int n = n0 + m;
            float4 a0 = make_float4(0.f, 0.f, 0.f, 0.f);
            float4 a1 = a0, a2 = a0, a3 = a0, xv = a0;
            if (n < NNODES) {
                xv = *(const float4*)(x + (size_t)n * HID + lane * 4);
                int beg = g_rowptr[n], end = g_rowptr[n + 1];
                #pragma unroll 4
                for (int e = beg; e < end; e++) {
                    int code = g_ecsr[e];
                    int et = code & 7;
                    float nv = g_norm[(n << 3) | et];
                    const float4 v = *(const float4*)(x + (size_t)(code >> 3) * HID + lane * 4);
                    float c0 = nv * comp_s[et * 4 + 0];
                    float c1 = nv * comp_s[et * 4 + 1];
                    float c2 = nv * comp_s[et * 4 + 2];
                    float c3 = nv * comp_s[et * 4 + 3];
                    a0.x = fmaf(c0, v.x, a0.x); a0.y = fmaf(c0, v.y, a0.y);
                    a0.z = fmaf(c0, v.z, a0.z); a0.w = fmaf(c0, v.w, a0.w);
                    a1.x = fmaf(c1, v.x, a1.x); a1.y = fmaf(c1, v.y, a1.y);
                    a1.z = fmaf(c1, v.z, a1.z); a1.w = fmaf(c1, v.w, a1.w);
                    a2.x = fmaf(c2, v.x, a2.x); a2.y = fmaf(c2, v.y, a2.y);
                    a2.z = fmaf(c2, v.z, a2.z); a2.w = fmaf(c2, v.w, a2.w);
                    a3.x = fmaf(c3, v.x, a3.x); a3.y = fmaf(c3, v.y, a3.y);
                    a3.z = fmaf(c3, v.z, a3.z); a3.w = fmaf(c3, v.w, a3.w);
                }
            }
            float* row = As + (size_t)m * KPAD;
            *(float4*)(row + 0 * 128 + lane * 4) = a0;
            *(float4*)(row + 1 * 128 + lane * 4) = a1;
            *(float4*)(row + 2 * 128 + lane * 4) = a2;
            *(float4*)(row + 3 * 128 + lane * 4) = a3;
            *(float4*)(row + 512 + lane * 4) = xv;
        }
    }
    __syncthreads();

    // ---- phase 2: GEMM 32xOUTD, K=640 ----
    constexpr int TN = OUTD / 32;          // 4 (OUTD=128) or 2 (OUTD=64)
    int tx = tid & 31, ty = tid >> 5;      // tx: 32 col-groups, ty: 8 row-groups
    float acc[4][TN] = {};
    for (int kt = 0; kt < KFUSE; kt += 16) {
        __syncthreads();
        if (OUTD == 128) {
            #pragma unroll
            for (int h = 0; h < 2; h++) {
                int e = tid * 4 + h * 1024;
                int r = e >> 7, c = e & 127;
                int k = kt + r;
                const float* src = (k < 512) ? bases + (size_t)k * OUTD + c
                                             : root + (size_t)(k - 512) * OUTD + c;
                *(float4*)(Bs + r * OUTD + c) = *(const float4*)src;
            }
        } else {
            int e = tid * 4;
            int r = e >> 6, c = e & 63;
            int k = kt + r;
            const float* src = (k < 512) ? bases + (size_t)k * OUTD + c
                                         : root + (size_t)(k - 512) * OUTD + c;
            *(float4*)(Bs + r * OUTD + c) = *(const float4*)src;
        }
        __syncthreads();
        #pragma unroll
        for (int kk = 0; kk < 16; kk++) {
            float av[4];
            #pragma unroll
            for (int i = 0; i < 4; i++)
                av[i] = As[(size_t)(ty * 4 + i) * KPAD + kt + kk];  // warp broadcast
            float bv[TN];
            if (TN == 4) {
                float4 b4 = *(float4*)(Bs + kk * OUTD + tx * 4);
                bv[0] = b4.x; bv[1] = b4.y; bv[2] = b4.z; bv[3] = b4.w;
            } else {
                float2 b2 = *(float2*)(Bs + kk * OUTD + tx * 2);
                bv[0] = b2.x; bv[1] = b2.y;
            }
            #pragma unroll
            for (int i = 0; i < 4; i++)
                #pragma unroll
                for (int j = 0; j < TN; j++)
                    acc[i][j] = fmaf(av[i], bv[j], acc[i][j]);
        }
    }

    // ---- epilogue ----
    #pragma unroll
    for (int i = 0; i < 4; i++) {
        int n = n0 + ty * 4 + i;
        if (n < NNODES) {
            #pragma unroll
            for (int j = 0; j < TN; j++) {
                int o = tx * TN + j;
                float v = acc[i][j] + bias[o];
                if (MODE == 0) v = fmaxf(v, 0.f);
                if (MODE == 1) v = fmaxf(v, 0.f) + resid[(size_t)n * OUTD + o];
                y[(size_t)n * OUTD + o] = v;
            }
        }
    }
}

// ---------------- launch ----------------------------------------------------
extern "C" void kernel_launch(void* const* d_in, const int* in_sizes, int n_in,
                              void* d_out, int out_size) {
    const float* x_paper  = (const float*)d_in[0];
    const float* x_author = (const float*)d_in[1];
    const float* W_paper  = (const float*)d_in[2];
    const float* b_paper  = (const float*)d_in[3];
    const float* W_author = (const float*)d_in[4];
    const float* b_author = (const float*)d_in[5];
    const float* bases0 = (const float*)d_in[6];
    const float* comp0  = (const float*)d_in[7];
    const float* root0  = (const float*)d_in[8];
    const float* bias0  = (const float*)d_in[9];
    const float* bases1 = (const float*)d_in[10];
    const float* comp1  = (const float*)d_in[11];
    const float* root1  = (const float*)d_in[12];
    const float* bias1  = (const float*)d_in[13];
    const float* bases2 = (const float*)d_in[14];
    const float* comp2  = (const float*)d_in[15];
    const float* root2  = (const float*)d_in[16];
    const float* bias2  = (const float*)d_in[17];
    const void*  edge_index = d_in[18];
    const void*  edge_type  = d_in[19];

    // output pytree flat order: out [N,64], x_init, x_init, h0 (each [N,128])
    float* out0 = (float*)d_out;
    float* lat0 = out0 + (size_t)NNODES * OUTD2;
    float* lat1 = lat0 + (size_t)NNODES * HID;
    float* lat2 = lat1 + (size_t)NNODES * HID;

    const int T = 256;
    const int gzero  = (NSEG + NNODES + T - 1) / T;
    const int gseg   = (NSEG + T - 1) / T;
    const int gedge  = (NEDGE + T - 1) / T;
    const int gproj  = (NPER + 63) / 64;
    const int gconv  = (NNODES + 31) / 32;

    const int smemA  = (32 * KPAD + 16 * HID + 32) * (int)sizeof(float);
    const int smemB  = (32 * KPAD + 16 * OUTD2 + 32) * (int)sizeof(float);

    cudaFuncSetAttribute(fused_conv<HID,   0, 0, 0>,
                         cudaFuncAttributeMaxDynamicSharedMemorySize, smemA);
    cudaFuncSetAttribute(fused_conv<HID,   1, 0, 1>,
                         cudaFuncAttributeMaxDynamicSharedMemorySize, smemA);
    cudaFuncSetAttribute(fused_conv<OUTD2, 2, 1, 0>,
                         cudaFuncAttributeMaxDynamicSharedMemorySize, smemB);

    // edge dtype + degree norm + CSR (once; reused by all three convs)
    detect_kernel<<<1, 32>>>((const int*)edge_index);
    zero_pre_kernel<<<gzero, T>>>();
    count_kernel<<<gedge, T>>>(edge_index, edge_type);
    norm_inv_kernel<<<gseg, T>>>();
    scan_kernel<<<1, 1024>>>();
    csr_fill_kernel<<<gedge, T>>>(edge_index, edge_type);

    // input projections -> x_init written to both latent slots
    proj_gemm<<<gproj, T>>>(x_paper, W_paper, b_paper, lat0, lat1);
    proj_gemm<<<gproj, T>>>(x_author, W_author, b_author,
                            lat0 + (size_t)NPER * HID, lat1 + (size_t)NPER * HID);

    // conv0: x = x_init (lat0) -> h0 = relu(.) -> lat2
    fused_conv<HID, 0, 0, 0><<<gconv, T, smemA>>>(
        lat0, comp0, bases0, root0, bias0, nullptr, lat2);

    // conv1: x = h0 (lat2) -> x2 = h0 + relu(.) -> g_x2
    fused_conv<HID, 1, 0, 1><<<gconv, T, smemA>>>(
        lat2, comp1, bases1, root1, bias1, lat2, nullptr);

    // conv2: x = g_x2 -> out (no relu) -> out0
    fused_conv<OUTD2, 2, 1, 0><<<gconv, T, smemB>>>(
        nullptr, comp2, bases2, root2, bias2, nullptr, out0);
}